// round 5
// baseline (speedup 1.0000x reference)
#include <cuda_runtime.h>
#include <math.h>
#include <stdint.h>

// Problem constants (match reference_code)
#define N_HITS 200000
#define DIM 8
#define P_IDS 512
#define NCLUST 511          // nonzero particle ids 1..511
#define NPAIR 256           // 512 clusters (1 dummy pad) as 256 packed pairs
#define Q_MIN 0.01f

// ---------------------------------------------------------------------------
// Device scratch (no allocations allowed -> __device__ globals)
// ---------------------------------------------------------------------------
__device__ double g_sum;                           // static-init 0
__device__ unsigned long long g_best[P_IDS];       // packed (q_bits<<32)|(~idx)
__device__ float g_q[N_HITS];                      // cached q per hit
__device__ int g_done_a;                           // block counter (argmax)
__device__ int g_done_m;                           // block counter (main)
// Pair-packed coefficients: pair j (clusters 2j, 2j+1), stride 20 floats:
//   float j*20 + 2*k + h : k=0..7 -> -2*xa_k ; k=8 -> |xa|^2 ; 18..19 unused
__device__ __align__(16) float g_pairc[NPAIR * 20];
__device__ float g_qa[P_IDS];                      // q_alpha per cluster (pad=0)

// ---------------------------------------------------------------------------
// Packed f32x2 helpers (sm_100+)
// ---------------------------------------------------------------------------
typedef unsigned long long u64;
__device__ __forceinline__ u64 fma2(u64 a, u64 b, u64 c) {
    u64 d;
    asm("fma.rn.f32x2 %0, %1, %2, %3;" : "=l"(d) : "l"(a), "l"(b), "l"(c));
    return d;
}
__device__ __forceinline__ u64 add2(u64 a, u64 b) {
    u64 d;
    asm("add.rn.f32x2 %0, %1, %2;" : "=l"(d) : "l"(a), "l"(b));
    return d;
}
__device__ __forceinline__ u64 bcast2(float x) {
    u64 r;
    asm("mov.b64 %0, {%1, %2};" : "=l"(r) : "f"(x), "f"(x));
    return r;
}
__device__ __forceinline__ void unpack2(u64 v, float& lo, float& hi) {
    asm("mov.b64 {%0, %1}, %2;" : "=f"(lo), "=f"(hi) : "l"(v));
}
__device__ __forceinline__ float lo2(u64 v) {
    float lo, hi;
    unpack2(v, lo, hi);
    return lo;
}
__device__ __forceinline__ u64 dbits(double d) { return __double_as_longlong(d); }

__device__ __forceinline__ float compute_q(float beta) {
    float a = atanhf(beta);
    return fmaf(a, a, Q_MIN);
}

// ---------------------------------------------------------------------------
// Kernel 1: q cache + per-cluster argmax via packed atomicMax; the LAST block
// then performs the representative gather (launch fusion).
// q >= 0.01 > 0 so float bits are monotone as unsigned; index complemented so
// q-ties pick the LOWER index (matches jnp.argmax). g_best==0 on entry
// (static init; re-zeroed in the gather phase each run).
// ---------------------------------------------------------------------------
#define ATPB 256

__global__ __launch_bounds__(ATPB) void k_argmax(const float* __restrict__ beta,
                                                 const int* __restrict__ pid,
                                                 const float* __restrict__ x) {
    int i = blockIdx.x * ATPB + threadIdx.x;
    if (i < N_HITS) {
        float q = compute_q(beta[i]);
        g_q[i] = q;
        int p = pid[i];
        if (p != 0) {
            u64 packed = ((u64)__float_as_uint(q) << 32) |
                         (u64)(0xFFFFFFFFu - (unsigned)i);
            atomicMax(&g_best[p], packed);
        }
    }
    // ---- last-block gather ----
    __threadfence();
    __syncthreads();
    __shared__ int s_last;
    if (threadIdx.x == 0)
        s_last = (atomicAdd(&g_done_a, 1) == (int)gridDim.x - 1);
    __syncthreads();
    if (!s_last) return;
    __threadfence();                                  // acquire

    for (int p = threadIdx.x; p < P_IDS; p += ATPB) { // p = cluster idx 0..511
        int j = p >> 1, h = p & 1;
        float* dst = g_pairc + j * 20;
        if (p == NCLUST) {                            // dummy pad cluster
#pragma unroll
            for (int k = 0; k < 8; k++) dst[2 * k + h] = 0.f;
            dst[16 + h] = 1e30f;                      // huge b -> hinge never
            g_qa[p] = 0.f;
            continue;
        }
        u64 packed = g_best[p + 1];
        g_best[p + 1] = 0ull;                         // reset for next replay
        int idx = (packed == 0ull)
                      ? 0
                      : (int)(0xFFFFFFFFu - (unsigned)(packed & 0xFFFFFFFFull));
        float b = 0.f;
#pragma unroll
        for (int k = 0; k < DIM; k++) {
            float v = x[idx * DIM + k];
            dst[2 * k + h] = -2.f * v;
            b = fmaf(v, v, b);
        }
        dst[16 + h] = b;
        g_qa[p] = g_q[idx];
    }
    if (threadIdx.x == 0) g_done_a = 0;               // reset counter
}

// ---------------------------------------------------------------------------
// Kernel 2: main loop. Each thread handles FOUR hits against 256 packed
// cluster pairs (f32x2 FMAs, 4 independent chains for latency hiding).
// sqrt path only when any of the 8 dist_sq < 1 (rare). Own-cluster fixups
// outside the loop. LAST block writes the final scalar (launch fusion).
// ---------------------------------------------------------------------------
#define TPB 128
#define NH 4
#define HPB (TPB * NH)

__global__ __launch_bounds__(TPB, 4) void k_main(const float* __restrict__ x,
                                                 const int* __restrict__ pid,
                                                 float* __restrict__ out) {
    __shared__ __align__(16) float s_c[NPAIR * 20];   // 20480 B
    __shared__ float s_q[P_IDS];                      // 2048 B
    {
        const float4* src = (const float4*)g_pairc;
        float4* dst = (float4*)s_c;
        for (int t = threadIdx.x; t < NPAIR * 5; t += TPB) dst[t] = src[t];
        for (int t = threadIdx.x; t < P_IDS; t += TPB) s_q[t] = g_qa[t];
    }
    __syncthreads();

    int ibase = blockIdx.x * HPB + threadIdx.x;
    float qh[NH];
    int pown[NH];
    u64 X[NH][8];     // broadcast-packed coords
    u64 SQ[NH];       // broadcast-packed |x|^2
#pragma unroll
    for (int h = 0; h < NH; h++) {
        int i = ibase + h * TPB;
        int ic = i < N_HITS ? i : N_HITS - 1;         // clamp tail
        qh[h] = (i < N_HITS) ? g_q[ic] : 0.f;
        pown[h] = (i < N_HITS) ? pid[ic] : 0;
        float4 v0 = *(const float4*)(x + (size_t)ic * DIM);
        float4 v1 = *(const float4*)(x + (size_t)ic * DIM + 4);
        float xsq = v0.x * v0.x + v0.y * v0.y + v0.z * v0.z + v0.w * v0.w
                  + v1.x * v1.x + v1.y * v1.y + v1.z * v1.z + v1.w * v1.w;
        X[h][0] = bcast2(v0.x); X[h][1] = bcast2(v0.y);
        X[h][2] = bcast2(v0.z); X[h][3] = bcast2(v0.w);
        X[h][4] = bcast2(v1.x); X[h][5] = bcast2(v1.y);
        X[h][6] = bcast2(v1.z); X[h][7] = bcast2(v1.w);
        SQ[h] = bcast2(xsq);
    }

    float rsum[NH];
#pragma unroll
    for (int h = 0; h < NH; h++) rsum[h] = 0.f;

#pragma unroll 2
    for (int j = 0; j < NPAIR; j++) {
        const float* base = s_c + j * 20;
        double2 c01 = *(const double2*)(base);
        double2 c23 = *(const double2*)(base + 4);
        double2 c45 = *(const double2*)(base + 8);
        double2 c67 = *(const double2*)(base + 12);
        u64 bp = *(const u64*)(base + 16);

        u64 acc[NH];
#pragma unroll
        for (int h = 0; h < NH; h++) acc[h] = add2(SQ[h], bp);
#pragma unroll
        for (int h = 0; h < NH; h++) acc[h] = fma2(dbits(c01.x), X[h][0], acc[h]);
#pragma unroll
        for (int h = 0; h < NH; h++) acc[h] = fma2(dbits(c01.y), X[h][1], acc[h]);
#pragma unroll
        for (int h = 0; h < NH; h++) acc[h] = fma2(dbits(c23.x), X[h][2], acc[h]);
#pragma unroll
        for (int h = 0; h < NH; h++) acc[h] = fma2(dbits(c23.y), X[h][3], acc[h]);
#pragma unroll
        for (int h = 0; h < NH; h++) acc[h] = fma2(dbits(c45.x), X[h][4], acc[h]);
#pragma unroll
        for (int h = 0; h < NH; h++) acc[h] = fma2(dbits(c45.y), X[h][5], acc[h]);
#pragma unroll
        for (int h = 0; h < NH; h++) acc[h] = fma2(dbits(c67.x), X[h][6], acc[h]);
#pragma unroll
        for (int h = 0; h < NH; h++) acc[h] = fma2(dbits(c67.y), X[h][7], acc[h]);

        float lo[NH], hi[NH];
#pragma unroll
        for (int h = 0; h < NH; h++) unpack2(acc[h], lo[h], hi[h]);
        float m = fminf(fminf(fminf(lo[0], hi[0]), fminf(lo[1], hi[1])),
                        fminf(fminf(lo[2], hi[2]), fminf(lo[3], hi[3])));
        if (m < 1.0f) {                        // rare (hinge active)
            float ql = s_q[2 * j], qr = s_q[2 * j + 1];
#pragma unroll
            for (int h = 0; h < NH; h++) {
                if (lo[h] < 1.0f)
                    rsum[h] = fmaf(1.0f - sqrtf(fmaxf(lo[h], 1e-12f)), ql, rsum[h]);
                if (hi[h] < 1.0f)
                    rsum[h] = fmaf(1.0f - sqrtf(fmaxf(hi[h], 1e-12f)), qr, rsum[h]);
            }
        }
    }

    // Own-cluster fixups (coords recovered from packed regs' lo halves)
    double v = 0.0;
#pragma unroll
    for (int h = 0; h < NH; h++) {
        float total = 10.f * rsum[h];
        if (pown[h] > 0) {
            int p = pown[h] - 1;
            const float* cf = s_c + (p >> 1) * 20 + (p & 1);
            float acc = lo2(SQ[h]) + cf[16];
            acc = fmaf(cf[0],  lo2(X[h][0]), acc);
            acc = fmaf(cf[2],  lo2(X[h][1]), acc);
            acc = fmaf(cf[4],  lo2(X[h][2]), acc);
            acc = fmaf(cf[6],  lo2(X[h][3]), acc);
            acc = fmaf(cf[8],  lo2(X[h][4]), acc);
            acc = fmaf(cf[10], lo2(X[h][5]), acc);
            acc = fmaf(cf[12], lo2(X[h][6]), acc);
            acc = fmaf(cf[14], lo2(X[h][7]), acc);
            acc = fmaxf(acc, 0.f);
            float dist = sqrtf(fmaxf(acc, 1e-12f));
            float hinge = fmaxf(1.f - dist, 0.f);
            total += (acc - 10.f * hinge) * s_q[p];
        }
        v += (double)(qh[h] * total);
    }

    // fp64 reduction: warp shuffle -> smem -> block -> one atomicAdd(double)
#pragma unroll
    for (int o = 16; o > 0; o >>= 1)
        v += __shfl_down_sync(0xffffffffu, v, o);

    __shared__ double s_part[TPB / 32];
    if ((threadIdx.x & 31) == 0) s_part[threadIdx.x >> 5] = v;
    __syncthreads();
    if (threadIdx.x == 0) {
        double w = 0.0;
#pragma unroll
        for (int k = 0; k < TPB / 32; k++) w += s_part[k];
        atomicAdd(&g_sum, w);
        // ---- last-block finalize ----
        if (atomicAdd(&g_done_m, 1) == (int)gridDim.x - 1) {
            double total = atomicAdd(&g_sum, 0.0);   // coherent read
            out[0] = (float)(total / (double)N_HITS);
            g_sum = 0.0;                              // reset for next replay
            g_done_m = 0;
        }
    }
}

// ---------------------------------------------------------------------------
// Launch: inputs in metadata order: w, beta, x, y, particle_id
// (w and y are unused by the reference loss)
// ---------------------------------------------------------------------------
extern "C" void kernel_launch(void* const* d_in, const int* in_sizes, int n_in,
                              void* d_out, int out_size) {
    const float* beta = (const float*)d_in[1];
    const float* x    = (const float*)d_in[2];
    const int*   pid  = (const int*)d_in[4];
    float* out = (float*)d_out;

    k_argmax<<<(N_HITS + ATPB - 1) / ATPB, ATPB>>>(beta, pid, x);
    k_main<<<(N_HITS + HPB - 1) / HPB, TPB>>>(x, pid, out);
}

// round 6
// speedup vs baseline: 1.0888x; 1.0888x over previous
#include <cuda_runtime.h>
#include <math.h>
#include <stdint.h>

// Problem constants (match reference_code)
#define N_HITS 200000
#define DIM 8
#define P_IDS 512
#define NCLUST 511          // nonzero particle ids 1..511
#define NPAIR 256           // 512 clusters (1 dummy pad) as 256 packed pairs
#define Q_MIN 0.01f

// ---------------------------------------------------------------------------
// Device scratch (no allocations allowed -> __device__ globals)
// ---------------------------------------------------------------------------
__device__ double g_sum;                           // static-init 0
__device__ unsigned long long g_best[P_IDS];       // packed (q_bits<<32)|(~idx)
__device__ float g_q[N_HITS];                      // cached q per hit
__device__ int g_done_a;                           // block counter (argmax)
__device__ int g_done_m;                           // block counter (main)
// Pair-packed coefficients: pair j (clusters 2j, 2j+1), stride 20 floats:
//   float j*20 + 2*k + h : k=0..7 -> -2*xa_k ; k=8 -> |xa|^2 ; 18..19 unused
__device__ __align__(16) float g_pairc[NPAIR * 20];
__device__ float g_qa[P_IDS];                      // q_alpha per cluster (pad=0)

// ---------------------------------------------------------------------------
// Packed f32x2 helpers (sm_100+)
// ---------------------------------------------------------------------------
typedef unsigned long long u64;
__device__ __forceinline__ u64 fma2(u64 a, u64 b, u64 c) {
    u64 d;
    asm("fma.rn.f32x2 %0, %1, %2, %3;" : "=l"(d) : "l"(a), "l"(b), "l"(c));
    return d;
}
__device__ __forceinline__ u64 bcast2(float x) {
    u64 r;
    asm("mov.b64 %0, {%1, %2};" : "=l"(r) : "f"(x), "f"(x));
    return r;
}
__device__ __forceinline__ void unpack2(u64 v, float& lo, float& hi) {
    asm("mov.b64 {%0, %1}, %2;" : "=f"(lo), "=f"(hi) : "l"(v));
}
__device__ __forceinline__ float lo2(u64 v) {
    float lo, hi;
    unpack2(v, lo, hi);
    return lo;
}
__device__ __forceinline__ u64 dbits(double d) { return __double_as_longlong(d); }

__device__ __forceinline__ float compute_q(float beta) {
    float a = atanhf(beta);
    return fmaf(a, a, Q_MIN);
}

// ---------------------------------------------------------------------------
// Kernel 1: q cache + per-cluster argmax via packed atomicMax; the LAST block
// then performs the representative gather (launch fusion).
// q >= 0.01 > 0 so float bits are monotone as unsigned; index complemented so
// q-ties pick the LOWER index (matches jnp.argmax). g_best==0 on entry
// (static init; re-zeroed in the gather phase each run).
// ---------------------------------------------------------------------------
#define ATPB 256

__global__ __launch_bounds__(ATPB) void k_argmax(const float* __restrict__ beta,
                                                 const int* __restrict__ pid,
                                                 const float* __restrict__ x) {
    int i = blockIdx.x * ATPB + threadIdx.x;
    if (i < N_HITS) {
        float q = compute_q(beta[i]);
        g_q[i] = q;
        int p = pid[i];
        if (p != 0) {
            u64 packed = ((u64)__float_as_uint(q) << 32) |
                         (u64)(0xFFFFFFFFu - (unsigned)i);
            atomicMax(&g_best[p], packed);
        }
    }
    // ---- last-block gather ----
    __threadfence();
    __syncthreads();
    __shared__ int s_last;
    if (threadIdx.x == 0)
        s_last = (atomicAdd(&g_done_a, 1) == (int)gridDim.x - 1);
    __syncthreads();
    if (!s_last) return;
    __threadfence();                                  // acquire

    for (int p = threadIdx.x; p < P_IDS; p += ATPB) { // p = cluster idx 0..511
        int j = p >> 1, h = p & 1;
        float* dst = g_pairc + j * 20;
        if (p == NCLUST) {                            // dummy pad cluster
#pragma unroll
            for (int k = 0; k < 8; k++) dst[2 * k + h] = 0.f;
            dst[16 + h] = 1e30f;                      // huge b -> hinge never
            g_qa[p] = 0.f;
            continue;
        }
        u64 packed = g_best[p + 1];
        g_best[p + 1] = 0ull;                         // reset for next replay
        int idx = (packed == 0ull)
                      ? 0
                      : (int)(0xFFFFFFFFu - (unsigned)(packed & 0xFFFFFFFFull));
        float b = 0.f;
#pragma unroll
        for (int k = 0; k < DIM; k++) {
            float v = x[idx * DIM + k];
            dst[2 * k + h] = -2.f * v;
            b = fmaf(v, v, b);
        }
        dst[16 + h] = b;
        g_qa[p] = g_q[idx];
    }
    if (threadIdx.x == 0) g_done_a = 0;               // reset counter
}

// ---------------------------------------------------------------------------
// Kernel 2: main loop. Grid = (hit groups) x (2 cluster halves). Each block
// handles HPB hits against 128 packed cluster pairs of its half. Doubled grid
// restores occupancy (R5 lesson). Inner chain computes t = b - 2*x.xa
// starting from b (no add2), screened against thr = 1 - |x|^2 (t < thr
// <=> dist^2 < 1). sqrt path rare. Own-cluster fixup applied only by the
// block whose half contains it. LAST block finalizes.
// ---------------------------------------------------------------------------
#define TPB 256
#define NH 2
#define HPB (TPB * NH)          // 512 hits per group
#define NGRP ((N_HITS + HPB - 1) / HPB)   // 391
#define PPH 128                 // pairs per half
#define CPH 256                 // clusters per half

__global__ __launch_bounds__(TPB, 4) void k_main(const float* __restrict__ x,
                                                 const int* __restrict__ pid,
                                                 float* __restrict__ out) {
    __shared__ __align__(16) float s_c[PPH * 20];     // 10240 B
    __shared__ float s_q[CPH];                        // 1024 B

    int grp = blockIdx.x >> 1;
    int hc  = blockIdx.x & 1;                         // cluster half 0/1
    {
        const float4* src = (const float4*)(g_pairc + hc * PPH * 20);
        float4* dst = (float4*)s_c;
        for (int t = threadIdx.x; t < PPH * 5; t += TPB) dst[t] = src[t];
        for (int t = threadIdx.x; t < CPH; t += TPB) s_q[t] = g_qa[hc * CPH + t];
    }
    __syncthreads();

    int ibase = grp * HPB + threadIdx.x;
    float qh[NH], xsq[NH], thr[NH];
    int pown[NH];
    u64 X[NH][8];     // broadcast-packed coords
#pragma unroll
    for (int h = 0; h < NH; h++) {
        int i = ibase + h * TPB;
        int ic = i < N_HITS ? i : N_HITS - 1;         // clamp tail
        qh[h] = (i < N_HITS) ? g_q[ic] : 0.f;
        pown[h] = (i < N_HITS) ? pid[ic] : 0;
        float4 v0 = *(const float4*)(x + (size_t)ic * DIM);
        float4 v1 = *(const float4*)(x + (size_t)ic * DIM + 4);
        float s = v0.x * v0.x + v0.y * v0.y + v0.z * v0.z + v0.w * v0.w
                + v1.x * v1.x + v1.y * v1.y + v1.z * v1.z + v1.w * v1.w;
        xsq[h] = s;
        thr[h] = 1.0f - s;
        X[h][0] = bcast2(v0.x); X[h][1] = bcast2(v0.y);
        X[h][2] = bcast2(v0.z); X[h][3] = bcast2(v0.w);
        X[h][4] = bcast2(v1.x); X[h][5] = bcast2(v1.y);
        X[h][6] = bcast2(v1.z); X[h][7] = bcast2(v1.w);
    }

    float rsum[NH];
#pragma unroll
    for (int h = 0; h < NH; h++) rsum[h] = 0.f;

#pragma unroll 2
    for (int j = 0; j < PPH; j++) {
        const float* base = s_c + j * 20;
        double2 c01 = *(const double2*)(base);
        double2 c23 = *(const double2*)(base + 4);
        double2 c45 = *(const double2*)(base + 8);
        double2 c67 = *(const double2*)(base + 12);
        u64 bp = *(const u64*)(base + 16);

        u64 acc[NH];
#pragma unroll
        for (int h = 0; h < NH; h++) acc[h] = fma2(dbits(c01.x), X[h][0], bp);
#pragma unroll
        for (int h = 0; h < NH; h++) acc[h] = fma2(dbits(c01.y), X[h][1], acc[h]);
#pragma unroll
        for (int h = 0; h < NH; h++) acc[h] = fma2(dbits(c23.x), X[h][2], acc[h]);
#pragma unroll
        for (int h = 0; h < NH; h++) acc[h] = fma2(dbits(c23.y), X[h][3], acc[h]);
#pragma unroll
        for (int h = 0; h < NH; h++) acc[h] = fma2(dbits(c45.x), X[h][4], acc[h]);
#pragma unroll
        for (int h = 0; h < NH; h++) acc[h] = fma2(dbits(c45.y), X[h][5], acc[h]);
#pragma unroll
        for (int h = 0; h < NH; h++) acc[h] = fma2(dbits(c67.x), X[h][6], acc[h]);
#pragma unroll
        for (int h = 0; h < NH; h++) acc[h] = fma2(dbits(c67.y), X[h][7], acc[h]);

        float lo0, hi0, lo1, hi1;
        unpack2(acc[0], lo0, hi0);
        unpack2(acc[1], lo1, hi1);
        float m0 = fminf(lo0, hi0);
        float m1 = fminf(lo1, hi1);
        if (m0 < thr[0] || m1 < thr[1]) {      // rare (hinge active)
            float ql = s_q[2 * j], qr = s_q[2 * j + 1];
            if (lo0 < thr[0]) {
                float d2 = fmaxf(xsq[0] + lo0, 0.f);
                rsum[0] = fmaf(1.0f - sqrtf(fmaxf(d2, 1e-12f)), ql, rsum[0]);
            }
            if (hi0 < thr[0]) {
                float d2 = fmaxf(xsq[0] + hi0, 0.f);
                rsum[0] = fmaf(1.0f - sqrtf(fmaxf(d2, 1e-12f)), qr, rsum[0]);
            }
            if (lo1 < thr[1]) {
                float d2 = fmaxf(xsq[1] + lo1, 0.f);
                rsum[1] = fmaf(1.0f - sqrtf(fmaxf(d2, 1e-12f)), ql, rsum[1]);
            }
            if (hi1 < thr[1]) {
                float d2 = fmaxf(xsq[1] + hi1, 0.f);
                rsum[1] = fmaf(1.0f - sqrtf(fmaxf(d2, 1e-12f)), qr, rsum[1]);
            }
        }
    }

    // Own-cluster fixups (only if own cluster lies in this block's half)
    double v = 0.0;
#pragma unroll
    for (int h = 0; h < NH; h++) {
        float total = 10.f * rsum[h];
        int c = pown[h] - 1;                  // global cluster index
        int cl = c - hc * CPH;                // local within half
        if (pown[h] > 0 && cl >= 0 && cl < CPH) {
            const float* cf = s_c + (cl >> 1) * 20 + (cl & 1);
            float acc = xsq[h] + cf[16];
            acc = fmaf(cf[0],  lo2(X[h][0]), acc);
            acc = fmaf(cf[2],  lo2(X[h][1]), acc);
            acc = fmaf(cf[4],  lo2(X[h][2]), acc);
            acc = fmaf(cf[6],  lo2(X[h][3]), acc);
            acc = fmaf(cf[8],  lo2(X[h][4]), acc);
            acc = fmaf(cf[10], lo2(X[h][5]), acc);
            acc = fmaf(cf[12], lo2(X[h][6]), acc);
            acc = fmaf(cf[14], lo2(X[h][7]), acc);
            acc = fmaxf(acc, 0.f);
            float dist = sqrtf(fmaxf(acc, 1e-12f));
            float hinge = fmaxf(1.f - dist, 0.f);
            total += (acc - 10.f * hinge) * s_q[cl];
        }
        v += (double)(qh[h] * total);
    }

    // fp64 reduction: warp shuffle -> smem -> block -> one atomicAdd(double)
#pragma unroll
    for (int o = 16; o > 0; o >>= 1)
        v += __shfl_down_sync(0xffffffffu, v, o);

    __shared__ double s_part[TPB / 32];
    if ((threadIdx.x & 31) == 0) s_part[threadIdx.x >> 5] = v;
    __syncthreads();
    if (threadIdx.x == 0) {
        double w = 0.0;
#pragma unroll
        for (int k = 0; k < TPB / 32; k++) w += s_part[k];
        atomicAdd(&g_sum, w);
        // ---- last-block finalize ----
        if (atomicAdd(&g_done_m, 1) == (int)gridDim.x - 1) {
            double total = atomicAdd(&g_sum, 0.0);   // coherent read
            out[0] = (float)(total / (double)N_HITS);
            g_sum = 0.0;                              // reset for next replay
            g_done_m = 0;
        }
    }
}

// ---------------------------------------------------------------------------
// Launch: inputs in metadata order: w, beta, x, y, particle_id
// (w and y are unused by the reference loss)
// ---------------------------------------------------------------------------
extern "C" void kernel_launch(void* const* d_in, const int* in_sizes, int n_in,
                              void* d_out, int out_size) {
    const float* beta = (const float*)d_in[1];
    const float* x    = (const float*)d_in[2];
    const int*   pid  = (const int*)d_in[4];
    float* out = (float*)d_out;

    k_argmax<<<(N_HITS + ATPB - 1) / ATPB, ATPB>>>(beta, pid, x);
    k_main<<<NGRP * 2, TPB>>>(x, pid, out);
}

// round 7
// speedup vs baseline: 1.1213x; 1.0299x over previous
#include <cuda_runtime.h>
#include <math.h>
#include <stdint.h>

// Problem constants (match reference_code)
#define N_HITS 200000
#define DIM 8
#define P_IDS 512
#define NCLUST 511          // nonzero particle ids 1..511
#define NPAIR 256           // 512 clusters (1 dummy pad) as 256 packed pairs
#define Q_MIN 0.01f

// ---------------------------------------------------------------------------
// Device scratch (no allocations allowed -> __device__ globals)
// ---------------------------------------------------------------------------
__device__ double g_sum;                           // static-init 0
__device__ unsigned long long g_best[P_IDS];       // packed (q_bits<<32)|(~idx)
__device__ float g_q[N_HITS];                      // cached q per hit
__device__ int g_done_a;                           // block counter (argmax)
__device__ int g_done_m;                           // block counter (main)
// Pair-packed coefficients: pair j (clusters 2j, 2j+1), stride 20 floats:
//   float j*20 + 2*k + h : k=0..7 -> -2*xa_k ; k=8 -> |xa|^2 ; 18..19 unused
__device__ __align__(16) float g_pairc[NPAIR * 20];
__device__ float g_qa[P_IDS];                      // q_alpha per cluster (pad=0)

// ---------------------------------------------------------------------------
// Packed f32x2 helpers (sm_100+)
// ---------------------------------------------------------------------------
typedef unsigned long long u64;
__device__ __forceinline__ u64 fma2(u64 a, u64 b, u64 c) {
    u64 d;
    asm("fma.rn.f32x2 %0, %1, %2, %3;" : "=l"(d) : "l"(a), "l"(b), "l"(c));
    return d;
}
__device__ __forceinline__ u64 bcast2(float x) {
    u64 r;
    asm("mov.b64 %0, {%1, %2};" : "=l"(r) : "f"(x), "f"(x));
    return r;
}
__device__ __forceinline__ void unpack2(u64 v, float& lo, float& hi) {
    asm("mov.b64 {%0, %1}, %2;" : "=f"(lo), "=f"(hi) : "l"(v));
}
__device__ __forceinline__ float lo2(u64 v) {
    float lo, hi;
    unpack2(v, lo, hi);
    return lo;
}
__device__ __forceinline__ u64 dbits(double d) { return __double_as_longlong(d); }

// Fast atanh: 0.5*ln((1+b)/(1-b)) via MUFU.LG2 + MUFU.RCP.
// beta in [0,1); rel err ~1e-6 -- far below the 1e-3 test threshold.
__device__ __forceinline__ float compute_q(float beta) {
    float r = __fdividef(1.0f + beta, 1.0f - beta);
    float a = 0.5f * __logf(r);
    return fmaf(a, a, Q_MIN);
}

// ---------------------------------------------------------------------------
// Kernel 1: q cache + per-cluster argmax via packed atomicMax; the LAST block
// then performs the representative gather (launch fusion).
// q >= 0.01 > 0 so float bits are monotone as unsigned; index complemented so
// q-ties pick the LOWER index (matches jnp.argmax). g_best==0 on entry
// (static init; re-zeroed in the gather phase each run).
// ---------------------------------------------------------------------------
#define ATPB 256

__global__ __launch_bounds__(ATPB) void k_argmax(const float* __restrict__ beta,
                                                 const int* __restrict__ pid,
                                                 const float* __restrict__ x) {
    int i = blockIdx.x * ATPB + threadIdx.x;
    if (i < N_HITS) {
        float q = compute_q(beta[i]);
        g_q[i] = q;
        int p = pid[i];
        if (p != 0) {
            u64 packed = ((u64)__float_as_uint(q) << 32) |
                         (u64)(0xFFFFFFFFu - (unsigned)i);
            atomicMax(&g_best[p], packed);
        }
    }
    // ---- last-block gather ----
    __threadfence();
    __syncthreads();
    __shared__ int s_last;
    if (threadIdx.x == 0)
        s_last = (atomicAdd(&g_done_a, 1) == (int)gridDim.x - 1);
    __syncthreads();
    if (!s_last) return;
    __threadfence();                                  // acquire

    for (int p = threadIdx.x; p < P_IDS; p += ATPB) { // p = cluster idx 0..511
        int j = p >> 1, h = p & 1;
        float* dst = g_pairc + j * 20;
        if (p == NCLUST) {                            // dummy pad cluster
#pragma unroll
            for (int k = 0; k < 8; k++) dst[2 * k + h] = 0.f;
            dst[16 + h] = 1e30f;                      // huge b -> hinge never
            g_qa[p] = 0.f;
            continue;
        }
        u64 packed = g_best[p + 1];
        g_best[p + 1] = 0ull;                         // reset for next replay
        int idx = (packed == 0ull)
                      ? 0
                      : (int)(0xFFFFFFFFu - (unsigned)(packed & 0xFFFFFFFFull));
        float b = 0.f;
#pragma unroll
        for (int k = 0; k < DIM; k++) {
            float v = x[idx * DIM + k];
            dst[2 * k + h] = -2.f * v;
            b = fmaf(v, v, b);
        }
        dst[16 + h] = b;
        g_qa[p] = g_q[idx];
    }
    if (threadIdx.x == 0) g_done_a = 0;               // reset counter
}

// ---------------------------------------------------------------------------
// Kernel 2: main loop. Grid = (hit groups) x (4 cluster quarters). Each block
// handles HPB hits against 64 packed cluster pairs. Quadrupled grid raises
// occupancy to the register limit (5 blocks/SM) and shrinks the wave tail
// (R6 lesson: blocks/SM was the binding resource). Inner chain computes
// t = b - 2*x.xa starting from b (no add2), screened against thr = 1 - |x|^2
// (t < thr <=> dist^2 < 1, rare). Own-cluster fixup applied only by the block
// whose quarter contains it. LAST block finalizes.
// ---------------------------------------------------------------------------
#define TPB 256
#define NH 2
#define HPB (TPB * NH)          // 512 hits per group
#define NGRP ((N_HITS + HPB - 1) / HPB)   // 391
#define NSPLIT 4                // cluster quarters
#define PPH (NPAIR / NSPLIT)    // 64 pairs per quarter
#define CPH (P_IDS / NSPLIT)    // 128 clusters per quarter

__global__ __launch_bounds__(TPB, 5) void k_main(const float* __restrict__ x,
                                                 const int* __restrict__ pid,
                                                 float* __restrict__ out) {
    __shared__ __align__(16) float s_c[PPH * 20];     // 5120 B
    __shared__ float s_q[CPH];                        // 512 B

    int grp = blockIdx.x >> 2;
    int hc  = blockIdx.x & 3;                         // cluster quarter 0..3
    {
        const float4* src = (const float4*)(g_pairc + hc * PPH * 20);
        float4* dst = (float4*)s_c;
        for (int t = threadIdx.x; t < PPH * 5; t += TPB) dst[t] = src[t];
        for (int t = threadIdx.x; t < CPH; t += TPB) s_q[t] = g_qa[hc * CPH + t];
    }
    __syncthreads();

    int ibase = grp * HPB + threadIdx.x;
    float qh[NH], xsq[NH], thr[NH];
    int pown[NH];
    u64 X[NH][8];     // broadcast-packed coords
#pragma unroll
    for (int h = 0; h < NH; h++) {
        int i = ibase + h * TPB;
        int ic = i < N_HITS ? i : N_HITS - 1;         // clamp tail
        qh[h] = (i < N_HITS) ? g_q[ic] : 0.f;
        pown[h] = (i < N_HITS) ? pid[ic] : 0;
        float4 v0 = *(const float4*)(x + (size_t)ic * DIM);
        float4 v1 = *(const float4*)(x + (size_t)ic * DIM + 4);
        float s = v0.x * v0.x + v0.y * v0.y + v0.z * v0.z + v0.w * v0.w
                + v1.x * v1.x + v1.y * v1.y + v1.z * v1.z + v1.w * v1.w;
        xsq[h] = s;
        thr[h] = 1.0f - s;
        X[h][0] = bcast2(v0.x); X[h][1] = bcast2(v0.y);
        X[h][2] = bcast2(v0.z); X[h][3] = bcast2(v0.w);
        X[h][4] = bcast2(v1.x); X[h][5] = bcast2(v1.y);
        X[h][6] = bcast2(v1.z); X[h][7] = bcast2(v1.w);
    }

    float rsum[NH];
#pragma unroll
    for (int h = 0; h < NH; h++) rsum[h] = 0.f;

#pragma unroll 2
    for (int j = 0; j < PPH; j++) {
        const float* base = s_c + j * 20;
        double2 c01 = *(const double2*)(base);
        double2 c23 = *(const double2*)(base + 4);
        double2 c45 = *(const double2*)(base + 8);
        double2 c67 = *(const double2*)(base + 12);
        u64 bp = *(const u64*)(base + 16);

        u64 acc[NH];
#pragma unroll
        for (int h = 0; h < NH; h++) acc[h] = fma2(dbits(c01.x), X[h][0], bp);
#pragma unroll
        for (int h = 0; h < NH; h++) acc[h] = fma2(dbits(c01.y), X[h][1], acc[h]);
#pragma unroll
        for (int h = 0; h < NH; h++) acc[h] = fma2(dbits(c23.x), X[h][2], acc[h]);
#pragma unroll
        for (int h = 0; h < NH; h++) acc[h] = fma2(dbits(c23.y), X[h][3], acc[h]);
#pragma unroll
        for (int h = 0; h < NH; h++) acc[h] = fma2(dbits(c45.x), X[h][4], acc[h]);
#pragma unroll
        for (int h = 0; h < NH; h++) acc[h] = fma2(dbits(c45.y), X[h][5], acc[h]);
#pragma unroll
        for (int h = 0; h < NH; h++) acc[h] = fma2(dbits(c67.x), X[h][6], acc[h]);
#pragma unroll
        for (int h = 0; h < NH; h++) acc[h] = fma2(dbits(c67.y), X[h][7], acc[h]);

        float lo0, hi0, lo1, hi1;
        unpack2(acc[0], lo0, hi0);
        unpack2(acc[1], lo1, hi1);
        float m0 = fminf(lo0, hi0);
        float m1 = fminf(lo1, hi1);
        if (m0 < thr[0] || m1 < thr[1]) {      // rare (hinge active)
            float ql = s_q[2 * j], qr = s_q[2 * j + 1];
            if (lo0 < thr[0]) {
                float d2 = fmaxf(xsq[0] + lo0, 0.f);
                rsum[0] = fmaf(1.0f - sqrtf(fmaxf(d2, 1e-12f)), ql, rsum[0]);
            }
            if (hi0 < thr[0]) {
                float d2 = fmaxf(xsq[0] + hi0, 0.f);
                rsum[0] = fmaf(1.0f - sqrtf(fmaxf(d2, 1e-12f)), qr, rsum[0]);
            }
            if (lo1 < thr[1]) {
                float d2 = fmaxf(xsq[1] + lo1, 0.f);
                rsum[1] = fmaf(1.0f - sqrtf(fmaxf(d2, 1e-12f)), ql, rsum[1]);
            }
            if (hi1 < thr[1]) {
                float d2 = fmaxf(xsq[1] + hi1, 0.f);
                rsum[1] = fmaf(1.0f - sqrtf(fmaxf(d2, 1e-12f)), qr, rsum[1]);
            }
        }
    }

    // Own-cluster fixups (only if own cluster lies in this block's quarter)
    double v = 0.0;
#pragma unroll
    for (int h = 0; h < NH; h++) {
        float total = 10.f * rsum[h];
        int c = pown[h] - 1;                  // global cluster index
        int cl = c - hc * CPH;                // local within quarter
        if (pown[h] > 0 && cl >= 0 && cl < CPH) {
            const float* cf = s_c + (cl >> 1) * 20 + (cl & 1);
            float acc = xsq[h] + cf[16];
            acc = fmaf(cf[0],  lo2(X[h][0]), acc);
            acc = fmaf(cf[2],  lo2(X[h][1]), acc);
            acc = fmaf(cf[4],  lo2(X[h][2]), acc);
            acc = fmaf(cf[6],  lo2(X[h][3]), acc);
            acc = fmaf(cf[8],  lo2(X[h][4]), acc);
            acc = fmaf(cf[10], lo2(X[h][5]), acc);
            acc = fmaf(cf[12], lo2(X[h][6]), acc);
            acc = fmaf(cf[14], lo2(X[h][7]), acc);
            acc = fmaxf(acc, 0.f);
            float dist = sqrtf(fmaxf(acc, 1e-12f));
            float hinge = fmaxf(1.f - dist, 0.f);
            total += (acc - 10.f * hinge) * s_q[cl];
        }
        v += (double)(qh[h] * total);
    }

    // fp64 reduction: warp shuffle -> smem -> block -> one atomicAdd(double)
#pragma unroll
    for (int o = 16; o > 0; o >>= 1)
        v += __shfl_down_sync(0xffffffffu, v, o);

    __shared__ double s_part[TPB / 32];
    if ((threadIdx.x & 31) == 0) s_part[threadIdx.x >> 5] = v;
    __syncthreads();
    if (threadIdx.x == 0) {
        double w = 0.0;
#pragma unroll
        for (int k = 0; k < TPB / 32; k++) w += s_part[k];
        atomicAdd(&g_sum, w);
        // ---- last-block finalize ----
        if (atomicAdd(&g_done_m, 1) == (int)gridDim.x - 1) {
            double total = atomicAdd(&g_sum, 0.0);   // coherent read
            out[0] = (float)(total / (double)N_HITS);
            g_sum = 0.0;                              // reset for next replay
            g_done_m = 0;
        }
    }
}

// ---------------------------------------------------------------------------
// Launch: inputs in metadata order: w, beta, x, y, particle_id
// (w and y are unused by the reference loss)
// ---------------------------------------------------------------------------
extern "C" void kernel_launch(void* const* d_in, const int* in_sizes, int n_in,
                              void* d_out, int out_size) {
    const float* beta = (const float*)d_in[1];
    const float* x    = (const float*)d_in[2];
    const int*   pid  = (const int*)d_in[4];
    float* out = (float*)d_out;

    k_argmax<<<(N_HITS + ATPB - 1) / ATPB, ATPB>>>(beta, pid, x);
    k_main<<<NGRP * NSPLIT, TPB>>>(x, pid, out);
}

// round 8
// speedup vs baseline: 1.3569x; 1.2101x over previous
#include <cuda_runtime.h>
#include <math.h>
#include <stdint.h>

// Problem constants (match reference_code)
#define N_HITS 200000
#define DIM 8
#define P_IDS 512
#define NCLUST 511          // nonzero particle ids 1..511
#define NPAIR 256           // 512 clusters (1 dummy pad) as 256 packed pairs
#define Q_MIN 0.01f

// ---------------------------------------------------------------------------
// Device scratch (no allocations allowed -> __device__ globals)
// ---------------------------------------------------------------------------
__device__ double g_sum;                           // static-init 0
__device__ unsigned long long g_best[P_IDS];       // packed (q_bits<<32)|(~idx)
__device__ int g_done_a;                           // block counter (argmax)
__device__ int g_done_m;                           // block counter (main)
// Pair-packed coefficients: pair j (clusters 2j, 2j+1), stride 20 floats:
//   float j*20 + 2*k + h : k=0..7 -> -2*xa_k ; k=8 -> |xa|^2 ; 18..19 unused
__device__ __align__(16) float g_pairc[NPAIR * 20];
__device__ float g_qa[P_IDS];                      // q_alpha per cluster (pad=0)

// ---------------------------------------------------------------------------
// Packed f32x2 helpers (sm_100+)
// ---------------------------------------------------------------------------
typedef unsigned long long u64;
__device__ __forceinline__ u64 fma2(u64 a, u64 b, u64 c) {
    u64 d;
    asm("fma.rn.f32x2 %0, %1, %2, %3;" : "=l"(d) : "l"(a), "l"(b), "l"(c));
    return d;
}
__device__ __forceinline__ u64 bcast2(float x) {
    u64 r;
    asm("mov.b64 %0, {%1, %2};" : "=l"(r) : "f"(x), "f"(x));
    return r;
}
__device__ __forceinline__ void unpack2(u64 v, float& lo, float& hi) {
    asm("mov.b64 {%0, %1}, %2;" : "=f"(lo), "=f"(hi) : "l"(v));
}
__device__ __forceinline__ float lo2(u64 v) {
    float lo, hi;
    unpack2(v, lo, hi);
    return lo;
}
__device__ __forceinline__ u64 dbits(double d) { return __double_as_longlong(d); }

// Fast atanh: 0.5*ln((1+b)/(1-b)) via MUFU.LG2 + MUFU.RCP.
// beta in [0,1); rel err ~1e-6 -- far below the 1e-3 test threshold.
__device__ __forceinline__ float compute_q(float beta) {
    float r = __fdividef(1.0f + beta, 1.0f - beta);
    float a = 0.5f * __logf(r);
    return fmaf(a, a, Q_MIN);
}

// ---------------------------------------------------------------------------
// Kernel 1: per-cluster argmax of q. Two-stage: shared-memory atomicMax
// pre-aggregation per block (spread banks, cheap), then one global atomicMax
// per touched cluster (~63k global atomics vs 200k direct). The LAST block
// performs the representative gather (launch fusion).
// q >= 0.01 > 0 so float bits are monotone as unsigned; index complemented so
// q-ties pick the LOWER index (matches jnp.argmax). g_best==0 on entry
// (static init; re-zeroed in the gather phase each run).
// ---------------------------------------------------------------------------
#define ATPB 1024

__global__ __launch_bounds__(ATPB) void k_argmax(const float* __restrict__ beta,
                                                 const int* __restrict__ pid,
                                                 const float* __restrict__ x) {
    __shared__ unsigned long long s_best[P_IDS];      // 4 KB
    if (threadIdx.x < P_IDS) s_best[threadIdx.x] = 0ull;
    __syncthreads();

    int i = blockIdx.x * ATPB + threadIdx.x;
    if (i < N_HITS) {
        int p = pid[i];
        if (p != 0) {
            float q = compute_q(beta[i]);
            u64 packed = ((u64)__float_as_uint(q) << 32) |
                         (u64)(0xFFFFFFFFu - (unsigned)i);
            atomicMax(&s_best[p], packed);
        }
    }
    __syncthreads();

    // Flush touched clusters to global
    if (threadIdx.x > 0 && threadIdx.x < P_IDS) {
        u64 v = s_best[threadIdx.x];
        if (v != 0ull) atomicMax(&g_best[threadIdx.x], v);
    }

    // ---- last-block gather ----
    __threadfence();
    __syncthreads();
    __shared__ int s_last;
    if (threadIdx.x == 0)
        s_last = (atomicAdd(&g_done_a, 1) == (int)gridDim.x - 1);
    __syncthreads();
    if (!s_last) return;
    __threadfence();                                  // acquire

    if (threadIdx.x < P_IDS) {
        int p = threadIdx.x;                          // cluster idx 0..511
        int j = p >> 1, h = p & 1;
        float* dst = g_pairc + j * 20;
        if (p == NCLUST) {                            // dummy pad cluster
#pragma unroll
            for (int k = 0; k < 8; k++) dst[2 * k + h] = 0.f;
            dst[16 + h] = 1e30f;                      // huge b -> hinge never
            g_qa[p] = 0.f;
        } else {
            u64 packed = g_best[p + 1];
            g_best[p + 1] = 0ull;                     // reset for next replay
            int idx = (packed == 0ull)
                          ? 0
                          : (int)(0xFFFFFFFFu - (unsigned)(packed & 0xFFFFFFFFull));
            float b = 0.f;
#pragma unroll
            for (int k = 0; k < DIM; k++) {
                float v = x[idx * DIM + k];
                dst[2 * k + h] = -2.f * v;
                b = fmaf(v, v, b);
            }
            dst[16 + h] = b;
            g_qa[p] = compute_q(beta[idx]);
        }
    }
    if (threadIdx.x == 0) g_done_a = 0;               // reset counter
}

// ---------------------------------------------------------------------------
// Kernel 2: main loop. Grid = (hit groups) x (4 cluster quarters). TPB=128 so
// the register limit admits ~11 blocks/SM (~44 warps, R7 lesson: occupancy was
// the binding constraint and TPB=256 capped it at 5 blocks = 40 warps). Each
// block: HPB hits vs 64 packed cluster pairs, f32x2 FMA chains seeded with b
// (no add2), screened against thr = 1 - |x|^2 (t < thr <=> dist^2 < 1, rare).
// Own-cluster fixup only in the owning quarter. LAST block finalizes.
// ---------------------------------------------------------------------------
#define TPB 128
#define NH 2
#define HPB (TPB * NH)          // 256 hits per group
#define NGRP ((N_HITS + HPB - 1) / HPB)   // 782
#define NSPLIT 4                // cluster quarters
#define PPH (NPAIR / NSPLIT)    // 64 pairs per quarter
#define CPH (P_IDS / NSPLIT)    // 128 clusters per quarter

__global__ __launch_bounds__(TPB) void k_main(const float* __restrict__ beta,
                                              const float* __restrict__ x,
                                              const int* __restrict__ pid,
                                              float* __restrict__ out) {
    __shared__ __align__(16) float s_c[PPH * 20];     // 5120 B
    __shared__ float s_q[CPH];                        // 512 B

    int grp = blockIdx.x >> 2;
    int hc  = blockIdx.x & 3;                         // cluster quarter 0..3
    {
        const float4* src = (const float4*)(g_pairc + hc * PPH * 20);
        float4* dst = (float4*)s_c;
        for (int t = threadIdx.x; t < PPH * 5; t += TPB) dst[t] = src[t];
        for (int t = threadIdx.x; t < CPH; t += TPB) s_q[t] = g_qa[hc * CPH + t];
    }
    __syncthreads();

    int ibase = grp * HPB + threadIdx.x;
    float xsq[NH], thr[NH];
    u64 X[NH][8];     // broadcast-packed coords
#pragma unroll
    for (int h = 0; h < NH; h++) {
        int i = ibase + h * TPB;
        int ic = i < N_HITS ? i : N_HITS - 1;         // clamp tail
        float4 v0 = *(const float4*)(x + (size_t)ic * DIM);
        float4 v1 = *(const float4*)(x + (size_t)ic * DIM + 4);
        float s = v0.x * v0.x + v0.y * v0.y + v0.z * v0.z + v0.w * v0.w
                + v1.x * v1.x + v1.y * v1.y + v1.z * v1.z + v1.w * v1.w;
        xsq[h] = s;
        thr[h] = 1.0f - s;
        X[h][0] = bcast2(v0.x); X[h][1] = bcast2(v0.y);
        X[h][2] = bcast2(v0.z); X[h][3] = bcast2(v0.w);
        X[h][4] = bcast2(v1.x); X[h][5] = bcast2(v1.y);
        X[h][6] = bcast2(v1.z); X[h][7] = bcast2(v1.w);
    }

    float rsum[NH];
#pragma unroll
    for (int h = 0; h < NH; h++) rsum[h] = 0.f;

#pragma unroll 2
    for (int j = 0; j < PPH; j++) {
        const float* base = s_c + j * 20;
        double2 c01 = *(const double2*)(base);
        double2 c23 = *(const double2*)(base + 4);
        double2 c45 = *(const double2*)(base + 8);
        double2 c67 = *(const double2*)(base + 12);
        u64 bp = *(const u64*)(base + 16);

        u64 acc[NH];
#pragma unroll
        for (int h = 0; h < NH; h++) acc[h] = fma2(dbits(c01.x), X[h][0], bp);
#pragma unroll
        for (int h = 0; h < NH; h++) acc[h] = fma2(dbits(c01.y), X[h][1], acc[h]);
#pragma unroll
        for (int h = 0; h < NH; h++) acc[h] = fma2(dbits(c23.x), X[h][2], acc[h]);
#pragma unroll
        for (int h = 0; h < NH; h++) acc[h] = fma2(dbits(c23.y), X[h][3], acc[h]);
#pragma unroll
        for (int h = 0; h < NH; h++) acc[h] = fma2(dbits(c45.x), X[h][4], acc[h]);
#pragma unroll
        for (int h = 0; h < NH; h++) acc[h] = fma2(dbits(c45.y), X[h][5], acc[h]);
#pragma unroll
        for (int h = 0; h < NH; h++) acc[h] = fma2(dbits(c67.x), X[h][6], acc[h]);
#pragma unroll
        for (int h = 0; h < NH; h++) acc[h] = fma2(dbits(c67.y), X[h][7], acc[h]);

        float lo0, hi0, lo1, hi1;
        unpack2(acc[0], lo0, hi0);
        unpack2(acc[1], lo1, hi1);
        float m0 = fminf(lo0, hi0);
        float m1 = fminf(lo1, hi1);
        if (m0 < thr[0] || m1 < thr[1]) {      // rare (hinge active)
            float ql = s_q[2 * j], qr = s_q[2 * j + 1];
            if (lo0 < thr[0]) {
                float d2 = fmaxf(xsq[0] + lo0, 0.f);
                rsum[0] = fmaf(1.0f - sqrtf(fmaxf(d2, 1e-12f)), ql, rsum[0]);
            }
            if (hi0 < thr[0]) {
                float d2 = fmaxf(xsq[0] + hi0, 0.f);
                rsum[0] = fmaf(1.0f - sqrtf(fmaxf(d2, 1e-12f)), qr, rsum[0]);
            }
            if (lo1 < thr[1]) {
                float d2 = fmaxf(xsq[1] + lo1, 0.f);
                rsum[1] = fmaf(1.0f - sqrtf(fmaxf(d2, 1e-12f)), ql, rsum[1]);
            }
            if (hi1 < thr[1]) {
                float d2 = fmaxf(xsq[1] + hi1, 0.f);
                rsum[1] = fmaf(1.0f - sqrtf(fmaxf(d2, 1e-12f)), qr, rsum[1]);
            }
        }
    }

    // Per-hit q / pid loaded AFTER the hot loop (lower live-reg pressure)
    double v = 0.0;
#pragma unroll
    for (int h = 0; h < NH; h++) {
        int i = ibase + h * TPB;
        int ic = i < N_HITS ? i : N_HITS - 1;
        float qh = (i < N_HITS) ? compute_q(beta[ic]) : 0.f;
        int pown = (i < N_HITS) ? pid[ic] : 0;

        float total = 10.f * rsum[h];
        int c = pown - 1;                     // global cluster index
        int cl = c - hc * CPH;                // local within quarter
        if (pown > 0 && cl >= 0 && cl < CPH) {
            const float* cf = s_c + (cl >> 1) * 20 + (cl & 1);
            float acc = xsq[h] + cf[16];
            acc = fmaf(cf[0],  lo2(X[h][0]), acc);
            acc = fmaf(cf[2],  lo2(X[h][1]), acc);
            acc = fmaf(cf[4],  lo2(X[h][2]), acc);
            acc = fmaf(cf[6],  lo2(X[h][3]), acc);
            acc = fmaf(cf[8],  lo2(X[h][4]), acc);
            acc = fmaf(cf[10], lo2(X[h][5]), acc);
            acc = fmaf(cf[12], lo2(X[h][6]), acc);
            acc = fmaf(cf[14], lo2(X[h][7]), acc);
            acc = fmaxf(acc, 0.f);
            float dist = sqrtf(fmaxf(acc, 1e-12f));
            float hinge = fmaxf(1.f - dist, 0.f);
            total += (acc - 10.f * hinge) * s_q[cl];
        }
        v += (double)(qh * total);
    }

    // fp64 reduction: warp shuffle -> smem -> block -> one atomicAdd(double)
#pragma unroll
    for (int o = 16; o > 0; o >>= 1)
        v += __shfl_down_sync(0xffffffffu, v, o);

    __shared__ double s_part[TPB / 32];
    if ((threadIdx.x & 31) == 0) s_part[threadIdx.x >> 5] = v;
    __syncthreads();
    if (threadIdx.x == 0) {
        double w = 0.0;
#pragma unroll
        for (int k = 0; k < TPB / 32; k++) w += s_part[k];
        atomicAdd(&g_sum, w);
        // ---- last-block finalize ----
        if (atomicAdd(&g_done_m, 1) == (int)gridDim.x - 1) {
            double total = atomicAdd(&g_sum, 0.0);   // coherent read
            out[0] = (float)(total / (double)N_HITS);
            g_sum = 0.0;                              // reset for next replay
            g_done_m = 0;
        }
    }
}

// ---------------------------------------------------------------------------
// Launch: inputs in metadata order: w, beta, x, y, particle_id
// (w and y are unused by the reference loss)
// ---------------------------------------------------------------------------
extern "C" void kernel_launch(void* const* d_in, const int* in_sizes, int n_in,
                              void* d_out, int out_size) {
    const float* beta = (const float*)d_in[1];
    const float* x    = (const float*)d_in[2];
    const int*   pid  = (const int*)d_in[4];
    float* out = (float*)d_out;

    k_argmax<<<(N_HITS + ATPB - 1) / ATPB, ATPB>>>(beta, pid, x);
    k_main<<<NGRP * NSPLIT, TPB>>>(beta, x, pid, out);
}

// round 10
// speedup vs baseline: 1.3576x; 1.0006x over previous
#include <cuda_runtime.h>
#include <math.h>
#include <stdint.h>

// Problem constants (match reference_code)
#define N_HITS 200000
#define DIM 8
#define P_IDS 512
#define NCLUST 511          // nonzero particle ids 1..511
#define NPAIR 256           // 512 clusters (1 dummy pad) as 256 packed pairs
#define Q_MIN 0.01f

// ---------------------------------------------------------------------------
// Device scratch (no allocations allowed -> __device__ globals)
// ---------------------------------------------------------------------------
__device__ double g_sum;                           // static-init 0
__device__ unsigned long long g_best[P_IDS];       // packed (q_bits<<32)|(~idx)
__device__ int g_done_a;                           // block counter (argmax)
__device__ int g_done_m;                           // block counter (main)
// Pair-packed coefficients: pair j (clusters 2j, 2j+1), stride 20 floats:
//   float j*20 + 2*k + h : k=0..7 -> -2*xa_k ; k=8 -> |xa|^2 ; 18..19 unused
__device__ __align__(16) float g_pairc[NPAIR * 20];
__device__ float g_qa[P_IDS];                      // q_alpha per cluster (pad=0)

// ---------------------------------------------------------------------------
// Packed f32x2 helpers (sm_100+)
// ---------------------------------------------------------------------------
typedef unsigned long long u64;
__device__ __forceinline__ u64 fma2(u64 a, u64 b, u64 c) {
    u64 d;
    asm("fma.rn.f32x2 %0, %1, %2, %3;" : "=l"(d) : "l"(a), "l"(b), "l"(c));
    return d;
}
__device__ __forceinline__ u64 bcast2(float x) {
    u64 r;
    asm("mov.b64 %0, {%1, %2};" : "=l"(r) : "f"(x), "f"(x));
    return r;
}
__device__ __forceinline__ void unpack2(u64 v, float& lo, float& hi) {
    asm("mov.b64 {%0, %1}, %2;" : "=f"(lo), "=f"(hi) : "l"(v));
}
__device__ __forceinline__ float lo2(u64 v) {
    float lo, hi;
    unpack2(v, lo, hi);
    return lo;
}
__device__ __forceinline__ u64 dbits(double d) { return __double_as_longlong(d); }

// Fast atanh: 0.5*ln((1+b)/(1-b)) via MUFU.LG2 + MUFU.RCP.
// beta in [0,1); rel err ~1e-6 -- far below the 1e-3 test threshold.
__device__ __forceinline__ float compute_q(float beta) {
    float r = __fdividef(1.0f + beta, 1.0f - beta);
    float a = 0.5f * __logf(r);
    return fmaf(a, a, Q_MIN);
}

// ---------------------------------------------------------------------------
// Kernel 1: per-cluster argmax of q. Two-stage: shared-memory atomicMax
// pre-aggregation per block, then one global atomicMax per touched cluster.
// The LAST block performs the representative gather (launch fusion).
// q >= 0.01 > 0 so float bits are monotone as unsigned; index complemented so
// q-ties pick the LOWER index (matches jnp.argmax). g_best==0 on entry
// (static init; re-zeroed in the gather phase each run).
// ---------------------------------------------------------------------------
#define ATPB 1024

__global__ __launch_bounds__(ATPB) void k_argmax(const float* __restrict__ beta,
                                                 const int* __restrict__ pid,
                                                 const float* __restrict__ x) {
    __shared__ unsigned long long s_best[P_IDS];      // 4 KB
    if (threadIdx.x < P_IDS) s_best[threadIdx.x] = 0ull;
    __syncthreads();

    int i = blockIdx.x * ATPB + threadIdx.x;
    if (i < N_HITS) {
        int p = pid[i];
        if (p != 0) {
            float q = compute_q(beta[i]);
            u64 packed = ((u64)__float_as_uint(q) << 32) |
                         (u64)(0xFFFFFFFFu - (unsigned)i);
            atomicMax(&s_best[p], packed);
        }
    }
    __syncthreads();

    // Flush touched clusters to global
    if (threadIdx.x > 0 && threadIdx.x < P_IDS) {
        u64 v = s_best[threadIdx.x];
        if (v != 0ull) atomicMax(&g_best[threadIdx.x], v);
    }

    // ---- last-block gather ----
    __threadfence();
    __syncthreads();
    __shared__ int s_last;
    if (threadIdx.x == 0)
        s_last = (atomicAdd(&g_done_a, 1) == (int)gridDim.x - 1);
    __syncthreads();
    if (!s_last) return;
    __threadfence();                                  // acquire

    if (threadIdx.x < P_IDS) {
        int p = threadIdx.x;                          // cluster idx 0..511
        int j = p >> 1, h = p & 1;
        float* dst = g_pairc + j * 20;
        if (p == NCLUST) {                            // dummy pad cluster
#pragma unroll
            for (int k = 0; k < 8; k++) dst[2 * k + h] = 0.f;
            dst[16 + h] = 1e30f;                      // huge b -> hinge never
            g_qa[p] = 0.f;
        } else {
            u64 packed = g_best[p + 1];
            g_best[p + 1] = 0ull;                     // reset for next replay
            int idx = (packed == 0ull)
                          ? 0
                          : (int)(0xFFFFFFFFu - (unsigned)(packed & 0xFFFFFFFFull));
            float b = 0.f;
#pragma unroll
            for (int k = 0; k < DIM; k++) {
                float v = x[idx * DIM + k];
                dst[2 * k + h] = -2.f * v;
                b = fmaf(v, v, b);
            }
            dst[16 + h] = b;
            g_qa[p] = compute_q(beta[idx]);
        }
    }
    if (threadIdx.x == 0) g_done_a = 0;               // reset counter
}

// ---------------------------------------------------------------------------
// Kernel 2: main loop. Grid = (hit groups) x (8 cluster eighths). TPB=128,
// 39 regs -> ~12 blocks/SM (~48 warps, 75% occ; R8 lesson: k_main pinned at
// ~50us across occ 44->60%, testing whether more overlap approaches the
// FFMA2 rt-3 banking floor ~37us). Each block: 256 hits vs 32 packed cluster
// pairs, f32x2 FMA chains seeded with b (no add2), screened against
// thr = 1 - |x|^2 (t < thr <=> dist^2 < 1, rare). Unroll 4 batches 20 LDS
// per stretch of 64 FMA2. Own-cluster fixup only in the owning eighth.
// LAST block finalizes.
// ---------------------------------------------------------------------------
#define TPB 128
#define NH 2
#define HPB (TPB * NH)          // 256 hits per group
#define NGRP ((N_HITS + HPB - 1) / HPB)   // 782
#define NSPLIT 8                // cluster eighths
#define PPH (NPAIR / NSPLIT)    // 32 pairs per eighth
#define CPH (P_IDS / NSPLIT)    // 64 clusters per eighth

__global__ __launch_bounds__(TPB) void k_main(const float* __restrict__ beta,
                                              const float* __restrict__ x,
                                              const int* __restrict__ pid,
                                              float* __restrict__ out) {
    __shared__ __align__(16) float s_c[PPH * 20];     // 2560 B
    __shared__ float s_q[CPH];                        // 256 B

    int grp = blockIdx.x >> 3;
    int hc  = blockIdx.x & 7;                         // cluster eighth 0..7
    {
        const float4* src = (const float4*)(g_pairc + hc * PPH * 20);
        float4* dst = (float4*)s_c;
        for (int t = threadIdx.x; t < PPH * 5; t += TPB) dst[t] = src[t];
        if (threadIdx.x < CPH) s_q[threadIdx.x] = g_qa[hc * CPH + threadIdx.x];
    }
    __syncthreads();

    int ibase = grp * HPB + threadIdx.x;
    float xsq[NH], thr[NH];
    u64 X[NH][8];     // broadcast-packed coords
#pragma unroll
    for (int h = 0; h < NH; h++) {
        int i = ibase + h * TPB;
        int ic = i < N_HITS ? i : N_HITS - 1;         // clamp tail
        float4 v0 = *(const float4*)(x + (size_t)ic * DIM);
        float4 v1 = *(const float4*)(x + (size_t)ic * DIM + 4);
        float s = v0.x * v0.x + v0.y * v0.y + v0.z * v0.z + v0.w * v0.w
                + v1.x * v1.x + v1.y * v1.y + v1.z * v1.z + v1.w * v1.w;
        xsq[h] = s;
        thr[h] = 1.0f - s;
        X[h][0] = bcast2(v0.x); X[h][1] = bcast2(v0.y);
        X[h][2] = bcast2(v0.z); X[h][3] = bcast2(v0.w);
        X[h][4] = bcast2(v1.x); X[h][5] = bcast2(v1.y);
        X[h][6] = bcast2(v1.z); X[h][7] = bcast2(v1.w);
    }

    float rsum[NH];
#pragma unroll
    for (int h = 0; h < NH; h++) rsum[h] = 0.f;

#pragma unroll 4
    for (int j = 0; j < PPH; j++) {
        const float* base = s_c + j * 20;
        double2 c01 = *(const double2*)(base);
        double2 c23 = *(const double2*)(base + 4);
        double2 c45 = *(const double2*)(base + 8);
        double2 c67 = *(const double2*)(base + 12);
        u64 bp = *(const u64*)(base + 16);

        u64 acc[NH];
#pragma unroll
        for (int h = 0; h < NH; h++) acc[h] = fma2(dbits(c01.x), X[h][0], bp);
#pragma unroll
        for (int h = 0; h < NH; h++) acc[h] = fma2(dbits(c01.y), X[h][1], acc[h]);
#pragma unroll
        for (int h = 0; h < NH; h++) acc[h] = fma2(dbits(c23.x), X[h][2], acc[h]);
#pragma unroll
        for (int h = 0; h < NH; h++) acc[h] = fma2(dbits(c23.y), X[h][3], acc[h]);
#pragma unroll
        for (int h = 0; h < NH; h++) acc[h] = fma2(dbits(c45.x), X[h][4], acc[h]);
#pragma unroll
        for (int h = 0; h < NH; h++) acc[h] = fma2(dbits(c45.y), X[h][5], acc[h]);
#pragma unroll
        for (int h = 0; h < NH; h++) acc[h] = fma2(dbits(c67.x), X[h][6], acc[h]);
#pragma unroll
        for (int h = 0; h < NH; h++) acc[h] = fma2(dbits(c67.y), X[h][7], acc[h]);

        float lo0, hi0, lo1, hi1;
        unpack2(acc[0], lo0, hi0);
        unpack2(acc[1], lo1, hi1);
        float m0 = fminf(lo0, hi0);
        float m1 = fminf(lo1, hi1);
        if (m0 < thr[0] || m1 < thr[1]) {      // rare (hinge active)
            float ql = s_q[2 * j], qr = s_q[2 * j + 1];
            if (lo0 < thr[0]) {
                float d2 = fmaxf(xsq[0] + lo0, 0.f);
                rsum[0] = fmaf(1.0f - sqrtf(fmaxf(d2, 1e-12f)), ql, rsum[0]);
            }
            if (hi0 < thr[0]) {
                float d2 = fmaxf(xsq[0] + hi0, 0.f);
                rsum[0] = fmaf(1.0f - sqrtf(fmaxf(d2, 1e-12f)), qr, rsum[0]);
            }
            if (lo1 < thr[1]) {
                float d2 = fmaxf(xsq[1] + lo1, 0.f);
                rsum[1] = fmaf(1.0f - sqrtf(fmaxf(d2, 1e-12f)), ql, rsum[1]);
            }
            if (hi1 < thr[1]) {
                float d2 = fmaxf(xsq[1] + hi1, 0.f);
                rsum[1] = fmaf(1.0f - sqrtf(fmaxf(d2, 1e-12f)), qr, rsum[1]);
            }
        }
    }

    // Per-hit q / pid loaded AFTER the hot loop (lower live-reg pressure)
    double v = 0.0;
#pragma unroll
    for (int h = 0; h < NH; h++) {
        int i = ibase + h * TPB;
        int ic = i < N_HITS ? i : N_HITS - 1;
        float qh = (i < N_HITS) ? compute_q(beta[ic]) : 0.f;
        int pown = (i < N_HITS) ? pid[ic] : 0;

        float total = 10.f * rsum[h];
        int c = pown - 1;                     // global cluster index
        int cl = c - hc * CPH;                // local within eighth
        if (pown > 0 && cl >= 0 && cl < CPH) {
            const float* cf = s_c + (cl >> 1) * 20 + (cl & 1);
            float acc = xsq[h] + cf[16];
            acc = fmaf(cf[0],  lo2(X[h][0]), acc);
            acc = fmaf(cf[2],  lo2(X[h][1]), acc);
            acc = fmaf(cf[4],  lo2(X[h][2]), acc);
            acc = fmaf(cf[6],  lo2(X[h][3]), acc);
            acc = fmaf(cf[8],  lo2(X[h][4]), acc);
            acc = fmaf(cf[10], lo2(X[h][5]), acc);
            acc = fmaf(cf[12], lo2(X[h][6]), acc);
            acc = fmaf(cf[14], lo2(X[h][7]), acc);
            acc = fmaxf(acc, 0.f);
            float dist = sqrtf(fmaxf(acc, 1e-12f));
            float hinge = fmaxf(1.f - dist, 0.f);
            total += (acc - 10.f * hinge) * s_q[cl];
        }
        v += (double)(qh * total);
    }

    // fp64 reduction: warp shuffle -> smem -> block -> one atomicAdd(double)
#pragma unroll
    for (int o = 16; o > 0; o >>= 1)
        v += __shfl_down_sync(0xffffffffu, v, o);

    __shared__ double s_part[TPB / 32];
    if ((threadIdx.x & 31) == 0) s_part[threadIdx.x >> 5] = v;
    __syncthreads();
    if (threadIdx.x == 0) {
        double w = 0.0;
#pragma unroll
        for (int k = 0; k < TPB / 32; k++) w += s_part[k];
        atomicAdd(&g_sum, w);
        // ---- last-block finalize ----
        if (atomicAdd(&g_done_m, 1) == (int)gridDim.x - 1) {
            double total = atomicAdd(&g_sum, 0.0);   // coherent read
            out[0] = (float)(total / (double)N_HITS);
            g_sum = 0.0;                              // reset for next replay
            g_done_m = 0;
        }
    }
}

// ---------------------------------------------------------------------------
// Launch: inputs in metadata order: w, beta, x, y, particle_id
// (w and y are unused by the reference loss)
// ---------------------------------------------------------------------------
extern "C" void kernel_launch(void* const* d_in, const int* in_sizes, int n_in,
                              void* d_out, int out_size) {
    const float* beta = (const float*)d_in[1];
    const float* x    = (const float*)d_in[2];
    const int*   pid  = (const int*)d_in[4];
    float* out = (float*)d_out;

    k_argmax<<<(N_HITS + ATPB - 1) / ATPB, ATPB>>>(beta, pid, x);
    k_main<<<NGRP * NSPLIT, TPB>>>(beta, x, pid, out);
}